// round 8
// baseline (speedup 1.0000x reference)
#include <cuda_runtime.h>

#define BATCH    512
#define NROWS    32
#define CDIM     1024
#define PITCH    1025
#define NTHREADS 512

struct Extra {
    unsigned long long red[16];
    float fred[16];
    int L[NROWS];
    int pa, pb, sm;
    float sqm;
};

#define XS_FLOATS   (NROWS * PITCH)
#define D2P_FLOATS  (32 * 33)
#define SQP_FLOATS  32
#define SMEM_FLOATS (XS_FLOATS + D2P_FLOATS + SQP_FLOATS)
#define SMEM_BYTES  (SMEM_FLOATS * 4 + (int)sizeof(Extra) + 16)

static __device__ __forceinline__ unsigned long long u64min(unsigned long long a, unsigned long long b) {
    return a < b ? a : b;
}

__global__ __launch_bounds__(NTHREADS, 1)
void agg_kernel(const float* __restrict__ x,
                const float* __restrict__ cw,
                const float* __restrict__ cb,
                float* __restrict__ out)
{
    extern __shared__ float smf[];
    float* xs  = smf;                    // 32 rows x pitch 1025
    float* d2p = smf + XS_FLOATS;        // 32x33 padded distance^2 (physical slots)
    float* sqp = d2p + D2P_FLOATS;       // 32 squared norms (physical slots)
    Extra* ex  = (Extra*)(sqp + SQP_FLOATS);

    const int tid = threadIdx.x;
    const int b   = blockIdx.x;

    const float w00 = cw[0], w01 = cw[1], w02 = cw[2];
    const float w10 = cw[3], w11 = cw[4], w12 = cw[5];
    const float bc  = cb[0];

    // ---- load this batch's 32x1024 into smem ----
    {
        const float4* src = (const float4*)(x + (size_t)b * NROWS * CDIM);
        #pragma unroll
        for (int k = 0; k < (NROWS*CDIM/4)/NTHREADS; k++) {
            int e4 = tid + k * NTHREADS;
            float4 v = src[e4];
            int e = e4 * 4;
            int r = e >> 10, c = e & (CDIM - 1);
            float* d = xs + r * PITCH + c;
            d[0] = v.x; d[1] = v.y; d[2] = v.z; d[3] = v.w;
        }
        for (int e = tid; e < D2P_FLOATS; e += NTHREADS) d2p[e] = 0.f;
        if (tid < NROWS) ex->L[tid] = tid;
    }
    __syncthreads();

    // ---- squared norms: 32 rows x 16 lanes each (all warps fully convergent) ----
    {
        int r = tid >> 4, lane = tid & 15;
        const float* row = xs + r * PITCH;
        float s = 0.f;
        #pragma unroll
        for (int k = 0; k < CDIM / 16; k++) { float v = row[lane + 16 * k]; s += v * v; }
        #pragma unroll
        for (int o = 8; o; o >>= 1) s += __shfl_down_sync(0xffffffffu, s, o, 16);
        if (lane == 0) sqp[r] = s;
    }

    // ---- 32x32 Gram matrix: 8 c-slices x (8x8 threads, 4x4 tiles) ----
    {
        int tslice = tid >> 6;       // 0..7 : c-slice
        int t64 = tid & 63;
        int ty = t64 >> 3, tx = t64 & 7;
        const float* rA0 = xs + (4 * ty + 0) * PITCH;
        const float* rA1 = xs + (4 * ty + 1) * PITCH;
        const float* rA2 = xs + (4 * ty + 2) * PITCH;
        const float* rA3 = xs + (4 * ty + 3) * PITCH;
        const float* rB0 = xs + (4 * tx + 0) * PITCH;
        const float* rB1 = xs + (4 * tx + 1) * PITCH;
        const float* rB2 = xs + (4 * tx + 2) * PITCH;
        const float* rB3 = xs + (4 * tx + 3) * PITCH;
        float acc[4][4];
        #pragma unroll
        for (int i = 0; i < 4; i++)
            #pragma unroll
            for (int j = 0; j < 4; j++) acc[i][j] = 0.f;

        int cbeg = tslice * (CDIM / 8);
        #pragma unroll 4
        for (int c = cbeg; c < cbeg + CDIM / 8; c++) {
            float a0 = rA0[c], a1 = rA1[c], a2 = rA2[c], a3 = rA3[c];
            float b0 = rB0[c], b1 = rB1[c], b2 = rB2[c], b3 = rB3[c];
            acc[0][0] += a0 * b0; acc[0][1] += a0 * b1; acc[0][2] += a0 * b2; acc[0][3] += a0 * b3;
            acc[1][0] += a1 * b0; acc[1][1] += a1 * b1; acc[1][2] += a1 * b2; acc[1][3] += a1 * b3;
            acc[2][0] += a2 * b0; acc[2][1] += a2 * b1; acc[2][2] += a2 * b2; acc[2][3] += a2 * b3;
            acc[3][0] += a3 * b0; acc[3][1] += a3 * b1; acc[3][2] += a3 * b2; acc[3][3] += a3 * b3;
        }
        // deterministic slice-ordered accumulation into d2p
        for (int s = 0; s < 8; s++) {
            if (tslice == s) {
                #pragma unroll
                for (int i = 0; i < 4; i++)
                    #pragma unroll
                    for (int j = 0; j < 4; j++)
                        d2p[(4 * ty + i) * 33 + (4 * tx + j)] += acc[i][j];
            }
            __syncthreads();
        }
        // finalize: d2 = |xi|^2 + |xj|^2 - 2 <xi,xj>
        for (int e = tid; e < 1024; e += NTHREADS) {
            int i = e >> 5, j = e & 31;
            float d = d2p[i * 33 + j];
            d2p[i * 33 + j] = sqp[i] + sqp[j] - 2.f * d;
        }
    }
    __syncthreads();

    // ---- 31 merge steps ----
    for (int n = NROWS; n >= 2; n--) {
        // argmin over logical pairs, flat-index tiebreak (matches reference row-major argmin)
        unsigned long long key = ~0ull;
        for (int f = tid; f < n * n; f += NTHREADS) {
            int i = f / n, j = f - i * n;
            if (i != j) {
                float v = fmaxf(d2p[ex->L[i] * 33 + ex->L[j]], 0.f);
                unsigned long long k = (((unsigned long long)__float_as_uint(v)) << 32) | (unsigned)f;
                key = u64min(key, k);
            }
        }
        #pragma unroll
        for (int o = 16; o; o >>= 1)
            key = u64min(key, __shfl_down_sync(0xffffffffu, key, o));
        if ((tid & 31) == 0) ex->red[tid >> 5] = key;
        __syncthreads();
        if (tid < 32) {
            unsigned long long k2 = (tid < 16) ? ex->red[tid] : ~0ull;
            #pragma unroll
            for (int o = 8; o; o >>= 1)
                k2 = u64min(k2, __shfl_down_sync(0xffffffffu, k2, o));
            if (tid == 0) {
                int f = (int)(k2 & 0xffffffffu);
                int a = f / n, bb = f - a * n;   // a < bb guaranteed (symmetry + flat order)
                int la0 = ex->L[0], la1 = ex->L[1];
                int pa = (a == 0) ? la0 : ((a == 1) ? la1 : ex->L[a]);
                int pb = (bb == 1) ? la1 : ex->L[bb];
                // replicate reference perm exactly (incl. a==1 duplicate/drop quirk):
                // remaining position p in [2, n-1] -> value (p==bb ? 1 : (a>=2 && p==a ? 0 : p))
                unsigned mask = 0u;
                for (int i = 1; i <= n - 2; i++) {
                    int p = i + 1;
                    int v = (p == bb) ? 1 : ((a >= 2 && p == a) ? 0 : p);
                    int sl = (v == 0) ? la0 : ((v == 1) ? la1 : ex->L[v]);
                    mask |= (1u << sl);
                    ex->L[i] = sl;
                }
                int sm = __ffs(~mask) - 1;   // lowest free physical slot
                ex->L[0] = sm;
                ex->pa = pa; ex->pb = pb; ex->sm = sm;
            }
        }
        __syncthreads();

        const int pa = ex->pa, pb = ex->pb, sm = ex->sm;
        const float* ra = xs + pa * PITCH;
        const float* rb = xs + pb * PITCH;
        const int c0 = 2 * tid;
        // conv1d k=3 SAME (cross-correlation, zero pad) over 2 input channels + bias + relu
        float am1 = (c0 == 0) ? 0.f : ra[c0 - 1];
        float a0 = ra[c0], a1 = ra[c0 + 1];
        float a2 = (c0 + 2 >= CDIM) ? 0.f : ra[c0 + 2];
        float bm1 = (c0 == 0) ? 0.f : rb[c0 - 1];
        float bv0 = rb[c0], bv1 = rb[c0 + 1];
        float bv2 = (c0 + 2 >= CDIM) ? 0.f : rb[c0 + 2];
        float m0 = bc + w00 * am1 + w01 * a0 + w02 * a1 + w10 * bm1 + w11 * bv0 + w12 * bv1;
        float m1 = bc + w00 * a0  + w01 * a1 + w02 * a2 + w10 * bv0 + w11 * bv1 + w12 * bv2;
        m0 = fmaxf(m0, 0.f); m1 = fmaxf(m1, 0.f);
        float sq = m0 * m0 + m1 * m1;
        #pragma unroll
        for (int o = 16; o; o >>= 1) sq += __shfl_down_sync(0xffffffffu, sq, o);
        if ((tid & 31) == 0) ex->fred[tid >> 5] = sq;
        __syncthreads();   // all reads of old rows pa/pb complete

        float* rm = xs + sm * PITCH;
        rm[c0] = m0; rm[c0 + 1] = m1;
        if (tid < 32) {
            float s2 = (tid < 16) ? ex->fred[tid] : 0.f;
            #pragma unroll
            for (int o = 8; o; o >>= 1) s2 += __shfl_down_sync(0xffffffffu, s2, o);
            if (tid == 0) { ex->sqm = s2; sqp[sm] = s2; }
        }
        __syncthreads();   // merged row + sqm visible

        // distance updates: one 16-thread group per surviving logical row.
        // FULLY CONVERGENT: every group runs the dot + shuffle (inactive groups
        // target slot sm harmlessly); only the final write is predicated.
        // (Previous version predicated the shuffle -> intra-warp sync-shuffle
        //  deadlock when one 16-group of a warp was inactive.)
        {
            int g = tid >> 4, lane = tid & 15;
            bool active = (g + 1 <= n - 2) || (g == 31);
            int t = (g + 1 <= n - 2) ? ex->L[g + 1] : sm;  // g==31 -> sm (diag refresh)
            const float* rt = xs + t * PITCH;
            float s = 0.f;
            #pragma unroll
            for (int k = 0; k < CDIM / 16; k++) {
                int c = lane + 16 * k;
                s += rm[c] * rt[c];
            }
            #pragma unroll
            for (int o = 8; o; o >>= 1) s += __shfl_down_sync(0xffffffffu, s, o, 16);
            if (active && lane == 0) {
                float d2 = ex->sqm + sqp[t] - 2.f * s;
                d2p[sm * 33 + t] = d2;
                d2p[t * 33 + sm] = d2;
            }
        }
        __syncthreads();
    }

    // ---- output: final merged row ----
    {
        const float* rf = xs + ex->L[0] * PITCH;
        float* ob = out + (size_t)b * CDIM;
        int c0 = 2 * tid;
        ob[c0]     = rf[c0];
        ob[c0 + 1] = rf[c0 + 1];
    }
}

extern "C" void kernel_launch(void* const* d_in, const int* in_sizes, int n_in,
                              void* d_out, int out_size)
{
    const float* x  = (const float*)d_in[0];
    const float* cw = (const float*)d_in[1];
    const float* cb = (const float*)d_in[2];
    float* out = (float*)d_out;
    cudaFuncSetAttribute(agg_kernel, cudaFuncAttributeMaxDynamicSharedMemorySize, SMEM_BYTES);
    agg_kernel<<<BATCH, NTHREADS, SMEM_BYTES>>>(x, cw, cb, out);
}

// round 10
// speedup vs baseline: 1.0289x; 1.0289x over previous
#include <cuda_runtime.h>

#define BATCH    512
#define NROWS    32
#define CDIM     1024
#define PITCH    1032          // multiple of 4 (16B alignment), +8 bank rotation per row
#define NTHREADS 512

struct Extra {
    unsigned long long red[16];
    float fred[16];
    int L[NROWS];
    int pa, pb, sm;
    float sqm;
};

#define XS_FLOATS   (NROWS * PITCH)
#define D2P_FLOATS  (32 * 33)
#define GTMP_FLOATS (8 * 1056)      // per-slice Gram scratch
#define SQP_FLOATS  32
#define SMEM_FLOATS (XS_FLOATS + D2P_FLOATS + GTMP_FLOATS + SQP_FLOATS)
#define SMEM_BYTES  (SMEM_FLOATS * 4 + (int)sizeof(Extra) + 16)

static __device__ __forceinline__ unsigned long long u64min(unsigned long long a, unsigned long long b) {
    return a < b ? a : b;
}

__global__ __launch_bounds__(NTHREADS, 1)
void agg_kernel(const float* __restrict__ x,
                const float* __restrict__ cw,
                const float* __restrict__ cb,
                float* __restrict__ out)
{
    extern __shared__ float smf[];
    float* xs   = smf;                      // 32 rows x pitch 1032
    float* d2p  = smf + XS_FLOATS;          // 32x33 distance^2 (physical slots)
    float* gtmp = d2p + D2P_FLOATS;         // 8 x 1056 Gram slice scratch
    float* sqp  = gtmp + GTMP_FLOATS;       // 32 squared norms (physical slots)
    Extra* ex   = (Extra*)(sqp + SQP_FLOATS);

    const int tid = threadIdx.x;
    const int b   = blockIdx.x;

    const float w00 = cw[0], w01 = cw[1], w02 = cw[2];
    const float w10 = cw[3], w11 = cw[4], w12 = cw[5];
    const float bc  = cb[0];

    // ---- load this batch's 32x1024 into smem (float4) ----
    {
        const float4* src = (const float4*)(x + (size_t)b * NROWS * CDIM);
        #pragma unroll
        for (int k = 0; k < (NROWS*CDIM/4)/NTHREADS; k++) {
            int e4 = tid + k * NTHREADS;
            float4 v = src[e4];
            int e = e4 * 4;
            int r = e >> 10, c = e & (CDIM - 1);
            *(float4*)(xs + r * PITCH + c) = v;
        }
        if (tid < NROWS) ex->L[tid] = tid;
    }
    __syncthreads();

    // ---- squared norms: 32 rows x 16 lanes each, float4 ----
    {
        int r = tid >> 4, lane = tid & 15;
        const float4* row = (const float4*)(xs + r * PITCH);
        float s = 0.f;
        #pragma unroll
        for (int k = 0; k < 16; k++) {
            float4 v = row[lane + 16 * k];
            s += v.x * v.x + v.y * v.y + v.z * v.z + v.w * v.w;
        }
        #pragma unroll
        for (int o = 8; o; o >>= 1) s += __shfl_down_sync(0xffffffffu, s, o, 16);
        if (lane == 0) sqp[r] = s;
    }

    // ---- 32x32 Gram: 8 c-slices x (8x8 threads, 4x4 tiles), float4 loads ----
    {
        int tslice = tid >> 6;       // 0..7 : c-slice of 128 floats = 32 float4
        int t64 = tid & 63;
        int ty = t64 >> 3, tx = t64 & 7;
        const float4* rA0 = (const float4*)(xs + (4 * ty + 0) * PITCH);
        const float4* rA1 = (const float4*)(xs + (4 * ty + 1) * PITCH);
        const float4* rA2 = (const float4*)(xs + (4 * ty + 2) * PITCH);
        const float4* rA3 = (const float4*)(xs + (4 * ty + 3) * PITCH);
        const float4* rB0 = (const float4*)(xs + (4 * tx + 0) * PITCH);
        const float4* rB1 = (const float4*)(xs + (4 * tx + 1) * PITCH);
        const float4* rB2 = (const float4*)(xs + (4 * tx + 2) * PITCH);
        const float4* rB3 = (const float4*)(xs + (4 * tx + 3) * PITCH);
        float acc[4][4];
        #pragma unroll
        for (int i = 0; i < 4; i++)
            #pragma unroll
            for (int j = 0; j < 4; j++) acc[i][j] = 0.f;

        int c4beg = tslice * 32;
        #pragma unroll 2
        for (int c4 = c4beg; c4 < c4beg + 32; c4++) {
            float4 a0 = rA0[c4], a1 = rA1[c4], a2 = rA2[c4], a3 = rA3[c4];
            float4 b0 = rB0[c4], b1 = rB1[c4], b2 = rB2[c4], b3 = rB3[c4];
            #define GRAM_STEP(C) { \
                float A0=a0.C, A1=a1.C, A2=a2.C, A3=a3.C; \
                float B0=b0.C, B1=b1.C, B2=b2.C, B3=b3.C; \
                acc[0][0]+=A0*B0; acc[0][1]+=A0*B1; acc[0][2]+=A0*B2; acc[0][3]+=A0*B3; \
                acc[1][0]+=A1*B0; acc[1][1]+=A1*B1; acc[1][2]+=A1*B2; acc[1][3]+=A1*B3; \
                acc[2][0]+=A2*B0; acc[2][1]+=A2*B1; acc[2][2]+=A2*B2; acc[2][3]+=A2*B3; \
                acc[3][0]+=A3*B0; acc[3][1]+=A3*B1; acc[3][2]+=A3*B2; acc[3][3]+=A3*B3; }
            GRAM_STEP(x) GRAM_STEP(y) GRAM_STEP(z) GRAM_STEP(w)
            #undef GRAM_STEP
        }
        // write per-slice partials to scratch
        float* gs = gtmp + tslice * 1056;
        #pragma unroll
        for (int i = 0; i < 4; i++)
            #pragma unroll
            for (int j = 0; j < 4; j++)
                gs[(4 * ty + i) * 33 + (4 * tx + j)] = acc[i][j];
    }
    __syncthreads();
    // deterministic 8-way reduce + finalize d2 = |xi|^2 + |xj|^2 - 2 <xi,xj>
    {
        for (int e = tid; e < 1024; e += NTHREADS) {
            int i = e >> 5, j = e & 31;
            int o = i * 33 + j;
            float d = gtmp[o];
            #pragma unroll
            for (int s = 1; s < 8; s++) d += gtmp[s * 1056 + o];
            d2p[o] = sqp[i] + sqp[j] - 2.f * d;
        }
    }
    __syncthreads();

    // ---- 31 merge steps ----
    for (int n = NROWS; n >= 2; n--) {
        // argmin over logical pairs (i,j), flat-index i*n+j tiebreak; no division
        {
            int i0 = tid >> 5, j = tid & 31;     // warp = fixed i0, j sweeps 0..31
            unsigned long long key = ~0ull;
            if (j < n) {
                int sj = ex->L[j];
                if (i0 < n && i0 != j) {
                    float v = fmaxf(d2p[ex->L[i0] * 33 + sj], 0.f);
                    key = (((unsigned long long)__float_as_uint(v)) << 32) | (unsigned)(i0 * n + j);
                }
                int i1 = i0 + 16;
                if (i1 < n && i1 != j) {
                    float v = fmaxf(d2p[ex->L[i1] * 33 + sj], 0.f);
                    unsigned long long k2 = (((unsigned long long)__float_as_uint(v)) << 32) | (unsigned)(i1 * n + j);
                    key = u64min(key, k2);
                }
            }
            #pragma unroll
            for (int o = 16; o; o >>= 1)
                key = u64min(key, __shfl_down_sync(0xffffffffu, key, o));
            if ((tid & 31) == 0) ex->red[tid >> 5] = key;
        }
        __syncthreads();
        if (tid < 32) {
            unsigned long long k2 = (tid < 16) ? ex->red[tid] : ~0ull;
            #pragma unroll
            for (int o = 8; o; o >>= 1)
                k2 = u64min(k2, __shfl_down_sync(0xffffffffu, k2, o));
            if (tid == 0) {
                int f = (int)(k2 & 0xffffffffu);
                int a = f / n, bb = f - a * n;   // a < bb guaranteed (symmetry + flat order)
                int la0 = ex->L[0], la1 = ex->L[1];
                int pa = (a == 0) ? la0 : ((a == 1) ? la1 : ex->L[a]);
                int pb = (bb == 1) ? la1 : ex->L[bb];
                // replicate reference perm exactly (incl. a==1 duplicate/drop quirk)
                unsigned mask = 0u;
                for (int i = 1; i <= n - 2; i++) {
                    int p = i + 1;
                    int v = (p == bb) ? 1 : ((a >= 2 && p == a) ? 0 : p);
                    int sl = (v == 0) ? la0 : ((v == 1) ? la1 : ex->L[v]);
                    mask |= (1u << sl);
                    ex->L[i] = sl;
                }
                int sm = __ffs(~mask) - 1;   // lowest free physical slot
                ex->L[0] = sm;
                ex->pa = pa; ex->pb = pb; ex->sm = sm;
            }
        }
        __syncthreads();

        const int pa = ex->pa, pb = ex->pb, sm = ex->sm;
        const float* ra = xs + pa * PITCH;
        const float* rb = xs + pb * PITCH;
        const int c0 = 2 * tid;
        // conv1d k=3 SAME over 2 input channels + bias + relu
        float am1 = (c0 == 0) ? 0.f : ra[c0 - 1];
        float a0 = ra[c0], a1 = ra[c0 + 1];
        float a2 = (c0 + 2 >= CDIM) ? 0.f : ra[c0 + 2];
        float bm1 = (c0 == 0) ? 0.f : rb[c0 - 1];
        float bv0 = rb[c0], bv1 = rb[c0 + 1];
        float bv2 = (c0 + 2 >= CDIM) ? 0.f : rb[c0 + 2];
        float m0 = bc + w00 * am1 + w01 * a0 + w02 * a1 + w10 * bm1 + w11 * bv0 + w12 * bv1;
        float m1 = bc + w00 * a0  + w01 * a1 + w02 * a2 + w10 * bv0 + w11 * bv1 + w12 * bv2;
        m0 = fmaxf(m0, 0.f); m1 = fmaxf(m1, 0.f);
        float sq = m0 * m0 + m1 * m1;
        #pragma unroll
        for (int o = 16; o; o >>= 1) sq += __shfl_down_sync(0xffffffffu, sq, o);
        if ((tid & 31) == 0) ex->fred[tid >> 5] = sq;
        __syncthreads();   // all reads of old rows pa/pb complete

        float* rm = xs + sm * PITCH;
        rm[c0] = m0; rm[c0 + 1] = m1;
        if (tid < 32) {
            float s2 = (tid < 16) ? ex->fred[tid] : 0.f;
            #pragma unroll
            for (int o = 8; o; o >>= 1) s2 += __shfl_down_sync(0xffffffffu, s2, o);
            if (tid == 0) { ex->sqm = s2; sqp[sm] = s2; }
        }
        __syncthreads();   // merged row + sqm visible

        // distance updates: 16-lane group per surviving logical row, float4 loads.
        // Loads are branch-skipped for inactive groups; the 16-wide shuffle stays
        // fully convergent (executed by ALL lanes — only loads/FMA are predicated).
        {
            int g = tid >> 4, lane = tid & 15;
            bool active_row = (g + 1 <= n - 2);
            bool act = active_row || (g == 31);          // g==31 -> diag refresh of sm
            int t = active_row ? ex->L[g + 1] : sm;
            float s = 0.f;
            if (act) {
                const float4* rt4 = (const float4*)(xs + t * PITCH);
                const float4* rm4 = (const float4*)rm;
                #pragma unroll
                for (int k = 0; k < 16; k++) {          // 16 iters x 16 lanes x 4 floats = 1024
                    int c = lane + 16 * k;
                    float4 u = rm4[c], v = rt4[c];
                    s += u.x * v.x + u.y * v.y + u.z * v.z + u.w * v.w;
                }
            }
            #pragma unroll
            for (int o = 8; o; o >>= 1) s += __shfl_down_sync(0xffffffffu, s, o, 16);
            if (act && lane == 0) {
                float d2 = ex->sqm + sqp[t] - 2.f * s;
                d2p[sm * 33 + t] = d2;
                d2p[t * 33 + sm] = d2;
            }
        }
        __syncthreads();
    }

    // ---- output: final merged row ----
    {
        const float* rf = xs + ex->L[0] * PITCH;
        float* ob = out + (size_t)b * CDIM;
        int c0 = 2 * tid;
        ob[c0]     = rf[c0];
        ob[c0 + 1] = rf[c0 + 1];
    }
}

extern "C" void kernel_launch(void* const* d_in, const int* in_sizes, int n_in,
                              void* d_out, int out_size)
{
    const float* x  = (const float*)d_in[0];
    const float* cw = (const float*)d_in[1];
    const float* cb = (const float*)d_in[2];
    float* out = (float*)d_out;
    cudaFuncSetAttribute(agg_kernel, cudaFuncAttributeMaxDynamicSharedMemorySize, SMEM_BYTES);
    agg_kernel<<<BATCH, NTHREADS, SMEM_BYTES>>>(x, cw, cb, out);
}

// round 11
// speedup vs baseline: 1.9240x; 1.8699x over previous
#include <cuda_runtime.h>

#define BATCH    512
#define NROWS    32
#define CDIM     1024
#define RPITCH   1032
#define NTHREADS 512
#define FULLM    0xffffffffu

// staggered row base (floats): rows 4 apart differ by 16B mod 128B -> conflict-free Gram
static __device__ __forceinline__ int rbase(int r) { return r * RPITCH + ((r >> 2) << 2); }

#define XS_FLOATS   (31 * RPITCH + 28 + RPITCH)   /* rbase(31)+RPITCH = 33052 */
#define D2P_FLOATS  (32 * 33)
#define GTMP_FLOATS (8 * 1056)
#define SQP_FLOATS  32
#define FRED_FLOATS 16
#define SMEM_FLOATS (XS_FLOATS + D2P_FLOATS + GTMP_FLOATS + SQP_FLOATS + FRED_FLOATS)
#define SMEM_BYTES  (SMEM_FLOATS * 4 + 16 * 8 + 32)

static __device__ __forceinline__ unsigned long long u64min(unsigned long long a, unsigned long long b) {
    return a < b ? a : b;
}

__global__ __launch_bounds__(NTHREADS, 1)
void agg_kernel(const float* __restrict__ x,
                const float* __restrict__ cw,
                const float* __restrict__ cb,
                float* __restrict__ out)
{
    extern __shared__ float smf[];
    float* xs   = smf;
    float* d2p  = smf + XS_FLOATS;
    float* gtmp = d2p + D2P_FLOATS;
    float* sqp  = gtmp + GTMP_FLOATS;
    float* fredS = sqp + SQP_FLOATS;
    unsigned long long* redS = (unsigned long long*)(fredS + FRED_FLOATS);

    const int tid  = threadIdx.x;
    const int w    = tid >> 5;
    const int lane = tid & 31;
    const int b    = blockIdx.x;

    const float w00 = cw[0], w01 = cw[1], w02 = cw[2];
    const float w10 = cw[3], w11 = cw[4], w12 = cw[5];
    const float bc  = cb[0];

    // ---- load batch rows into staggered smem ----
    {
        const float4* src = (const float4*)(x + (size_t)b * NROWS * CDIM);
        #pragma unroll
        for (int k = 0; k < (NROWS*CDIM/4)/NTHREADS; k++) {
            int e4 = tid + k * NTHREADS;
            float4 v = src[e4];
            int e = e4 * 4;
            int r = e >> 10, c = e & (CDIM - 1);
            *(float4*)(xs + rbase(r) + c) = v;
        }
    }
    __syncthreads();

    // ---- squared norms: 32 rows x 16 lanes ----
    {
        int r = tid >> 4, l16 = tid & 15;
        const float4* row = (const float4*)(xs + rbase(r));
        float s = 0.f;
        #pragma unroll
        for (int k = 0; k < 16; k++) {
            float4 v = row[l16 + 16 * k];
            s += v.x * v.x + v.y * v.y + v.z * v.z + v.w * v.w;
        }
        #pragma unroll
        for (int o = 8; o; o >>= 1) s += __shfl_down_sync(FULLM, s, o, 16);
        if (l16 == 0) sqp[r] = s;
    }

    // ---- 32x32 Gram: 8 c-slices x (8x8 threads, 4x4 tiles), conflict-free ----
    {
        int tslice = tid >> 6;
        int t64 = tid & 63;
        int ty = t64 >> 3, tx = t64 & 7;
        const float4* rA0 = (const float4*)(xs + rbase(4 * ty + 0));
        const float4* rA1 = (const float4*)(xs + rbase(4 * ty + 1));
        const float4* rA2 = (const float4*)(xs + rbase(4 * ty + 2));
        const float4* rA3 = (const float4*)(xs + rbase(4 * ty + 3));
        const float4* rB0 = (const float4*)(xs + rbase(4 * tx + 0));
        const float4* rB1 = (const float4*)(xs + rbase(4 * tx + 1));
        const float4* rB2 = (const float4*)(xs + rbase(4 * tx + 2));
        const float4* rB3 = (const float4*)(xs + rbase(4 * tx + 3));
        float acc[4][4];
        #pragma unroll
        for (int i = 0; i < 4; i++)
            #pragma unroll
            for (int j = 0; j < 4; j++) acc[i][j] = 0.f;

        int c4beg = tslice * 32;
        #pragma unroll 2
        for (int c4 = c4beg; c4 < c4beg + 32; c4++) {
            float4 a0 = rA0[c4], a1 = rA1[c4], a2 = rA2[c4], a3 = rA3[c4];
            float4 b0 = rB0[c4], b1 = rB1[c4], b2 = rB2[c4], b3 = rB3[c4];
            #define GRAM_STEP(C) { \
                float A0=a0.C, A1=a1.C, A2=a2.C, A3=a3.C; \
                float B0=b0.C, B1=b1.C, B2=b2.C, B3=b3.C; \
                acc[0][0]+=A0*B0; acc[0][1]+=A0*B1; acc[0][2]+=A0*B2; acc[0][3]+=A0*B3; \
                acc[1][0]+=A1*B0; acc[1][1]+=A1*B1; acc[1][2]+=A1*B2; acc[1][3]+=A1*B3; \
                acc[2][0]+=A2*B0; acc[2][1]+=A2*B1; acc[2][2]+=A2*B2; acc[2][3]+=A2*B3; \
                acc[3][0]+=A3*B0; acc[3][1]+=A3*B1; acc[3][2]+=A3*B2; acc[3][3]+=A3*B3; }
            GRAM_STEP(x) GRAM_STEP(y) GRAM_STEP(z) GRAM_STEP(w)
            #undef GRAM_STEP
        }
        float* gs = gtmp + tslice * 1056;
        #pragma unroll
        for (int i = 0; i < 4; i++)
            #pragma unroll
            for (int j = 0; j < 4; j++)
                gs[(4 * ty + i) * 33 + (4 * tx + j)] = acc[i][j];
    }
    __syncthreads();
    // deterministic 8-way reduce + finalize
    for (int e = tid; e < 1024; e += NTHREADS) {
        int i = e >> 5, j = e & 31;
        int o = i * 33 + j;
        float d = gtmp[o];
        #pragma unroll
        for (int s = 1; s < 8; s++) d += gtmp[s * 1056 + o];
        d2p[o] = sqp[i] + sqp[j] - 2.f * d;
    }
    __syncthreads();

    // register-replicated logical->physical slot table: lane l holds L[l]
    int myL = lane;

    // ---- merge steps ----
    for (int n = NROWS; n >= 2; n--) {
        int a, bb;
        if (n > 2) {
            // (A) argmin: warp w covers rows i=w and i=w+16, lane = col j
            unsigned long long key = ~0ull;
            {
                int Lj = myL;
                int i0 = w, i1 = w + 16;
                int Li0 = __shfl_sync(FULLM, myL, i0);
                int Li1 = __shfl_sync(FULLM, myL, i1);
                if (lane < n && i0 != lane) {   // i0 = w < 16 < n (n>2..32: if n<=16, i0 may be >= n)
                    if (i0 < n) {
                        float v = fmaxf(d2p[Li0 * 33 + Lj], 0.f);
                        key = (((unsigned long long)__float_as_uint(v)) << 32) | (unsigned)((i0 << 8) | lane);
                    }
                }
                if (lane < n && i1 < n && i1 != lane) {
                    float v = fmaxf(d2p[Li1 * 33 + Lj], 0.f);
                    unsigned long long k2 = (((unsigned long long)__float_as_uint(v)) << 32) | (unsigned)((i1 << 8) | lane);
                    key = u64min(key, k2);
                }
                #pragma unroll
                for (int o = 16; o; o >>= 1)
                    key = u64min(key, __shfl_xor_sync(FULLM, key, o));
                if (lane == 0) redS[w] = key;
            }
            __syncthreads();                                   // BAR1
            {
                unsigned long long v = redS[lane & 15];
                #pragma unroll
                for (int o = 8; o; o >>= 1)
                    v = u64min(v, __shfl_xor_sync(FULLM, v, o));
                a  = (int)((v >> 8) & 0xff);
                bb = (int)(v & 0xff);
            }
        } else {
            a = 0; bb = 1;
        }

        // perm update, fully in registers, redundantly per warp (identical results)
        int pa, pb, sm;
        {
            int oldL = myL;
            int la0 = __shfl_sync(FULLM, oldL, 0);
            int la1 = __shfl_sync(FULLM, oldL, 1);
            pa = (a == 0) ? la0 : ((a == 1) ? la1 : __shfl_sync(FULLM, oldL, a));
            pb = (bb == 1) ? la1 : __shfl_sync(FULLM, oldL, bb);
            int p = lane + 1;
            int v = (p == bb) ? 1 : ((a >= 2 && p == a) ? 0 : p);
            int slv = __shfl_sync(FULLM, oldL, v & 31);
            unsigned bit = (lane >= 1 && lane <= n - 2) ? (1u << slv) : 0u;
            unsigned mask = __reduce_or_sync(FULLM, bit);
            sm = __ffs(~mask) - 1;
            if (lane == 0) myL = sm;
            else if (lane <= n - 2) myL = slv;
        }

        // (C) conv1d k=3 SAME over rows pa,pb + bias + relu; float2 + shuffles
        const float* ra = xs + rbase(pa);
        const float* rb = xs + rbase(pb);
        const int c0 = 2 * tid;
        float2 Av = ((const float2*)ra)[tid];
        float2 Bv = ((const float2*)rb)[tid];
        float am1 = __shfl_up_sync(FULLM, Av.y, 1);
        float bm1 = __shfl_up_sync(FULLM, Bv.y, 1);
        float a2  = __shfl_down_sync(FULLM, Av.x, 1);
        float bv2 = __shfl_down_sync(FULLM, Bv.x, 1);
        if (lane == 0)  { am1 = (tid == 0) ? 0.f : ra[c0 - 1];
                          bm1 = (tid == 0) ? 0.f : rb[c0 - 1]; }
        if (lane == 31) { a2  = (tid == NTHREADS - 1) ? 0.f : ra[c0 + 2];
                          bv2 = (tid == NTHREADS - 1) ? 0.f : rb[c0 + 2]; }
        float m0 = bc + w00 * am1  + w01 * Av.x + w02 * Av.y + w10 * bm1  + w11 * Bv.x + w12 * Bv.y;
        float m1 = bc + w00 * Av.x + w01 * Av.y + w02 * a2   + w10 * Bv.x + w11 * Bv.y + w12 * bv2;
        m0 = fmaxf(m0, 0.f); m1 = fmaxf(m1, 0.f);

        if (n == 2) {
            // final merged row goes straight to output from registers
            float* ob = out + (size_t)b * CDIM;
            ((float2*)ob)[tid] = make_float2(m0, m1);
            break;
        }

        float sq = m0 * m0 + m1 * m1;
        #pragma unroll
        for (int o = 16; o; o >>= 1) sq += __shfl_down_sync(FULLM, sq, o);
        if (lane == 0) fredS[w] = sq;
        __syncthreads();                                       // BAR3 (conv reads done, fred ready)

        // (D) write merged row; all warps compute sqm from fred
        float* rm = xs + rbase(sm);
        ((float2*)rm)[tid] = make_float2(m0, m1);
        float sqm;
        {
            float v = fredS[lane & 15];
            #pragma unroll
            for (int o = 8; o; o >>= 1) v += __shfl_xor_sync(FULLM, v, o);
            sqm = v;
        }
        if (tid == 0) sqp[sm] = sqm;
        __syncthreads();                                       // BAR4 (rm + sqp[sm] visible)

        // (E) distance updates: warp w handles logical targets w+1 and w+17;
        // warp 15 refreshes the diagonal when its second slot is free.
        {
            int l1 = w + 1, l2 = w + 17;
            bool v1 = (l1 <= n - 2);
            bool v2 = (l2 <= n - 2);
            bool dg = (!v2 && w == 15);
            int t1 = __shfl_sync(FULLM, myL, l1 & 31);
            int t2 = v2 ? __shfl_sync(FULLM, myL, l2 & 31) : sm;
            const float4* rm4 = (const float4*)rm;
            float4 rmv[8];
            float s1 = 0.f, s2 = 0.f;
            if (v1 || v2 || dg) {
                #pragma unroll
                for (int k = 0; k < 8; k++) rmv[k] = rm4[lane + 32 * k];
            }
            if (v1) {
                const float4* rt = (const float4*)(xs + rbase(t1));
                #pragma unroll
                for (int k = 0; k < 8; k++) {
                    float4 v = rt[lane + 32 * k];
                    s1 += rmv[k].x * v.x + rmv[k].y * v.y + rmv[k].z * v.z + rmv[k].w * v.w;
                }
            }
            if (v2 || dg) {
                const float4* rt = (const float4*)(xs + rbase(t2));
                #pragma unroll
                for (int k = 0; k < 8; k++) {
                    float4 v = rt[lane + 32 * k];
                    s2 += rmv[k].x * v.x + rmv[k].y * v.y + rmv[k].z * v.z + rmv[k].w * v.w;
                }
            }
            #pragma unroll
            for (int o = 16; o; o >>= 1) {
                s1 += __shfl_xor_sync(FULLM, s1, o);
                s2 += __shfl_xor_sync(FULLM, s2, o);
            }
            if (lane == 0) {
                if (v1) {
                    float d2 = sqm + sqp[t1] - 2.f * s1;
                    d2p[sm * 33 + t1] = d2;
                    d2p[t1 * 33 + sm] = d2;
                }
                if (v2 || dg) {
                    float d2 = sqm + sqp[t2] - 2.f * s2;
                    d2p[sm * 33 + t2] = d2;
                    d2p[t2 * 33 + sm] = d2;
                }
            }
        }
        __syncthreads();                                       // BAR5 (d2p ready for next argmin)
    }
}

extern "C" void kernel_launch(void* const* d_in, const int* in_sizes, int n_in,
                              void* d_out, int out_size)
{
    const float* x  = (const float*)d_in[0];
    const float* cw = (const float*)d_in[1];
    const float* cb = (const float*)d_in[2];
    float* out = (float*)d_out;
    cudaFuncSetAttribute(agg_kernel, cudaFuncAttributeMaxDynamicSharedMemorySize, SMEM_BYTES);
    agg_kernel<<<BATCH, NTHREADS, SMEM_BYTES>>>(x, cw, cb, out);
}